// round 14
// baseline (speedup 1.0000x reference)
#include <cuda_runtime.h>
#include <cuda_fp16.h>
#include <math.h>
#include <cstdint>

// Problem constants
#define BATCH 4
#define SEQ   4096
#define DIM   512
#define KEXP  8
#define ROWS  (BATCH*SEQ)        // 16384 token rows
#define CHUNK 64                 // scan chunk length
#define NCHUNK (SEQ/CHUNK)       // 64 chunks
#define INV_TAU (1.0f/16.0f)
#define LN_EPS 1e-5f

// ---------------------------------------------------------------------------
// Scratch (static device globals)
// ---------------------------------------------------------------------------
__device__ float g_i[ROWS * DIM];                       // x @ W_i (fp32)
__device__ float g_e[ROWS * KEXP];
__device__ float g_s[ROWS * KEXP];
__device__ float g_S[BATCH * NCHUNK * KEXP * DIM];
__device__ float g_P[BATCH * NCHUNK * KEXP * DIM];
__device__ __half g_xh[ROWS * DIM];                     // fp16(x)
__device__ __half g_yh[ROWS * DIM];                     // fp16(LN(y))
__device__ __half g_wi[DIM * DIM];                      // W_i^T  [N,K] fp16
__device__ __half g_wo[DIM * DIM];                      // W_out^T [N,K] fp16
__device__ __half g_wes[16 * DIM];                      // [W_e|W_s]^T [16,K] fp16

// ---------------------------------------------------------------------------
// PTX primitives (baseline sm_80+ — legal for compute_103 PTX target)
// ---------------------------------------------------------------------------
__device__ __forceinline__ uint32_t smem_to_u32(const void* p) {
    uint32_t a;
    asm("{ .reg .u64 t; cvta.to.shared.u64 t, %1; cvt.u32.u64 %0, t; }" : "=r"(a) : "l"(p));
    return a;
}

__device__ __forceinline__ void cp16(uint32_t dst, const void* src) {
    asm volatile("cp.async.cg.shared.global [%0], [%1], 16;" :: "r"(dst), "l"(src));
}
__device__ __forceinline__ void cp_commit() {
    asm volatile("cp.async.commit_group;" ::: "memory");
}
template <int N>
__device__ __forceinline__ void cp_wait() {
    asm volatile("cp.async.wait_group %0;" :: "n"(N) : "memory");
}

__device__ __forceinline__ void ldsm4(uint32_t* r, uint32_t addr) {
    asm volatile("ldmatrix.sync.aligned.m8n8.x4.shared.b16 {%0,%1,%2,%3}, [%4];"
                 : "=r"(r[0]), "=r"(r[1]), "=r"(r[2]), "=r"(r[3]) : "r"(addr));
}

__device__ __forceinline__ void mma16816(float* c, const uint32_t* a, const uint32_t* b) {
    asm volatile(
        "mma.sync.aligned.m16n8k16.row.col.f32.f16.f16.f32 "
        "{%0,%1,%2,%3}, {%4,%5,%6,%7}, {%8,%9}, {%0,%1,%2,%3};"
        : "+f"(c[0]), "+f"(c[1]), "+f"(c[2]), "+f"(c[3])
        : "r"(a[0]), "r"(a[1]), "r"(a[2]), "r"(a[3]), "r"(b[0]), "r"(b[1]));
}

// Swizzle: XOR bits[4:5] with bits[7:8], applied to the FINAL 16B-chunk offset.
__device__ __forceinline__ uint32_t swz(uint32_t off) {
    return off ^ (((off >> 7) & 3u) << 4);
}

// ---------------------------------------------------------------------------
// HMMA fp16 GEMM (unchanged)
// ---------------------------------------------------------------------------
#define BK 32
#define NKI (DIM/BK)             // 16 k-iterations
#define GTILE_B 8192             // bytes per tile (128 rows x 64B)
#define GSTAGES 3

struct __align__(128) GemmSmem { char buf[GSTAGES][2][GTILE_B]; };  // 48 KB

__device__ __forceinline__ void gemm_load(uint32_t sbase, int stage, int c,
                                          const __half* A, const __half* B,
                                          int row0, int col0, int tid) {
    const int r = tid >> 1;
    const int h = tid & 1;
    const uint32_t so0 = swz((uint32_t)(r * 64 + h * 32));
    const uint32_t so1 = swz((uint32_t)(r * 64 + h * 32 + 16));
    const size_t ga = (size_t)(row0 + r) * DIM + c * BK + h * 16;
    const size_t gb = (size_t)(col0 + r) * DIM + c * BK + h * 16;
    const uint32_t base = sbase + (uint32_t)(stage * 2 * GTILE_B);
    cp16(base + 0 * GTILE_B + so0, A + ga);
    cp16(base + 0 * GTILE_B + so1, A + ga + 8);
    cp16(base + 1 * GTILE_B + so0, B + gb);
    cp16(base + 1 * GTILE_B + so1, B + gb + 8);
}

__device__ __forceinline__ void gemm_body(const __half* __restrict__ A,
                                          const __half* __restrict__ B,
                                          float* __restrict__ C) {
    __shared__ GemmSmem sm;
    const uint32_t sbase = smem_to_u32(&sm);
    const int tid = threadIdx.x;
    const int lane = tid & 31;
    const int wid = tid >> 5;
    const int warp_m = wid >> 1;
    const int warp_n = wid & 1;
    const int row0 = blockIdx.y * 128;
    const int col0 = blockIdx.x * 128;

    const int lr = lane & 15;
    const int lc = (lane >> 4) & 1;

    float acc[2][8][4];
    #pragma unroll
    for (int m = 0; m < 2; m++)
        #pragma unroll
        for (int n = 0; n < 8; n++)
            #pragma unroll
            for (int q = 0; q < 4; q++) acc[m][n][q] = 0.0f;

    #pragma unroll
    for (int s = 0; s < GSTAGES - 1; ++s) {
        gemm_load(sbase, s, s, A, B, row0, col0, tid);
        cp_commit();
    }

    uint32_t aAddr[2][2], bAddr[4][2];
    #pragma unroll
    for (int m = 0; m < 2; m++)
        #pragma unroll
        for (int kk = 0; kk < 2; kk++)
            aAddr[m][kk] = swz((uint32_t)((warp_m * 32 + m * 16 + lr) * 64
                                          + lc * 16 + kk * 32));
    #pragma unroll
    for (int q = 0; q < 4; q++)
        #pragma unroll
        for (int kk = 0; kk < 2; kk++)
            bAddr[q][kk] = swz((uint32_t)((warp_n * 64 + q * 16 + lr) * 64
                                          + lc * 16 + kk * 32));

    for (int c = 0; c < NKI; ++c) {
        cp_wait<GSTAGES - 2>();
        __syncthreads();

        if (c + GSTAGES - 1 < NKI)
            gemm_load(sbase, (c + GSTAGES - 1) % GSTAGES, c + GSTAGES - 1,
                      A, B, row0, col0, tid);
        cp_commit();

        const uint32_t bb = sbase + (uint32_t)((c % GSTAGES) * 2 * GTILE_B);

        #pragma unroll
        for (int kk = 0; kk < 2; ++kk) {
            uint32_t a[2][4], b[8][2];
            #pragma unroll
            for (int q = 0; q < 4; q++) {
                uint32_t t4[4];
                ldsm4(t4, bb + 1 * GTILE_B + bAddr[q][kk]);
                b[2*q][0] = t4[0]; b[2*q+1][0] = t4[1];
                b[2*q][1] = t4[2]; b[2*q+1][1] = t4[3];
            }
            ldsm4(a[0], bb + aAddr[0][kk]);
            ldsm4(a[1], bb + aAddr[1][kk]);
            #pragma unroll
            for (int m = 0; m < 2; m++)
                #pragma unroll
                for (int n = 0; n < 8; n++) mma16816(acc[m][n], a[m], b[n]);
        }
    }

    const int tr = lane >> 2;
    const int tc = (lane & 3) * 2;
    #pragma unroll
    for (int m = 0; m < 2; m++) {
        const int rbase = row0 + warp_m * 32 + m * 16 + tr;
        #pragma unroll
        for (int n = 0; n < 8; n++) {
            const int col = col0 + warp_n * 64 + n * 8 + tc;
            float* p0 = C + (size_t)rbase * DIM + col;
            float* p1 = C + (size_t)(rbase + 8) * DIM + col;
            *(float2*)p0 = make_float2(acc[m][n][0], acc[m][n][1]);
            *(float2*)p1 = make_float2(acc[m][n][2], acc[m][n][3]);
        }
    }
}

__global__ __launch_bounds__(256, 2) void gemm1_kernel() {
    gemm_body(g_xh, g_wi, g_i);
}
__global__ __launch_bounds__(256, 2) void gemm2_kernel(float* __restrict__ out) {
    gemm_body(g_yh, g_wo, out);
}

// ---------------------------------------------------------------------------
// es via HMMA (unchanged)
// ---------------------------------------------------------------------------
#define ETILE_B 4096
#define ES_PITCH 520
#define ESTAGES 3
#define ENKI 32

struct __align__(128) EsSmem {
    char abuf[ESTAGES][ETILE_B];
    __half w[16 * ES_PITCH];
};

__device__ __forceinline__ void es_load(uint32_t sbase, int stage, int c,
                                        int row0, int r) {
    #pragma unroll
    for (int h = 0; h < 2; ++h) {
        cp16(sbase + (uint32_t)(stage * ETILE_B)
                   + swz((uint32_t)(r * 32 + h * 16)),
             g_xh + (size_t)(row0 + r) * DIM + c * 16 + h * 8);
    }
}

__global__ __launch_bounds__(128, 4) void es_mma_kernel() {
    __shared__ EsSmem sm;
    const uint32_t sbase = smem_to_u32(&sm);
    const uint32_t wbase = smem_to_u32(sm.w);
    const int tid = threadIdx.x;
    const int lane = tid & 31;
    const int wid = tid >> 5;
    const int row0 = blockIdx.x * 128;
    const int r = tid;

    {
        const int row = tid >> 3;
        const int colb = (tid & 7) * 64;
        #pragma unroll
        for (int q = 0; q < 8; ++q) {
            uint4 v = *(const uint4*)(g_wes + row * DIM + colb + q * 8);
            *(uint4*)(sm.w + row * ES_PITCH + colb + q * 8) = v;
        }
    }

    #pragma unroll
    for (int s = 0; s < ESTAGES - 1; ++s) {
        es_load(sbase, s, s, row0, r);
        cp_commit();
    }

    const int lr = lane & 15;
    const int lc = (lane >> 4) & 1;
    uint32_t aAddr[2];
    #pragma unroll
    for (int m = 0; m < 2; m++)
        aAddr[m] = swz((uint32_t)((wid * 32 + m * 16 + lr) * 32 + lc * 16));

    float acc[2][2][4];
    #pragma unroll
    for (int m = 0; m < 2; m++)
        #pragma unroll
        for (int n = 0; n < 2; n++)
            #pragma unroll
            for (int q = 0; q < 4; q++) acc[m][n][q] = 0.0f;

    for (int c = 0; c < ENKI; ++c) {
        cp_wait<ESTAGES - 2>();
        __syncthreads();

        if (c + ESTAGES - 1 < ENKI) {
            int st = (c + ESTAGES - 1) % ESTAGES;
            es_load(sbase, st, c + ESTAGES - 1, row0, r);
        }
        cp_commit();

        uint32_t b[2][2];
        #pragma unroll
        for (int nt = 0; nt < 2; ++nt) {
            const uint32_t base = wbase
                + (uint32_t)(((nt * 8 + (lane >> 2)) * ES_PITCH + c * 16 + (lane & 3) * 2) * 2);
            asm volatile("ld.shared.b32 %0, [%1];" : "=r"(b[nt][0]) : "r"(base));
            asm volatile("ld.shared.b32 %0, [%1];" : "=r"(b[nt][1]) : "r"(base + 16));
        }

        const uint32_t ab = sbase + (uint32_t)((c % ESTAGES) * ETILE_B);
        uint32_t a[4];
        #pragma unroll
        for (int m = 0; m < 2; m++) {
            ldsm4(a, ab + aAddr[m]);
            mma16816(acc[m][0], a, b[0]);
            mma16816(acc[m][1], a, b[1]);
        }
    }

    const int tr = lane >> 2;
    const int tc = (lane & 3) * 2;
    #pragma unroll
    for (int m = 0; m < 2; m++) {
        const int rbase = row0 + wid * 32 + m * 16 + tr;
        #pragma unroll
        for (int nt = 0; nt < 2; nt++) {
            float* dst = nt ? g_s : g_e;
            *(float2*)(dst + (size_t)rbase * KEXP + tc) =
                make_float2(acc[m][nt][0], acc[m][nt][1]);
            *(float2*)(dst + (size_t)(rbase + 8) * KEXP + tc) =
                make_float2(acc[m][nt][2], acc[m][nt][3]);
        }
    }
}

// ---------------------------------------------------------------------------
// Fused conversions (unchanged)
// ---------------------------------------------------------------------------
#define CVT_XBLOCKS (ROWS * DIM / 4 / 256)   // 8192

__global__ __launch_bounds__(256) void convert_all_kernel(
        const float* __restrict__ x,
        const float* __restrict__ W_i, const float* __restrict__ W_out,
        const float* __restrict__ W_e, const float* __restrict__ W_s) {
    __shared__ float t[32][33];
    const int bid = blockIdx.x;
    const int tid = threadIdx.x;

    if (bid < CVT_XBLOCKS) {
        const size_t i = (size_t)bid * 256 + tid;
        float4 v = ((const float4*)x)[i];
        __half h[4];
        h[0] = __float2half(v.x);
        h[1] = __float2half(v.y);
        h[2] = __float2half(v.z);
        h[3] = __float2half(v.w);
        ((uint2*)g_xh)[i] = *(uint2*)h;
    } else if (bid < CVT_XBLOCKS + 512) {
        const int idx = bid - CVT_XBLOCKS;
        const int z = idx >> 8;
        const float* W = z ? W_out : W_i;
        __half* D = z ? g_wo : g_wi;
        const int n0 = (idx & 15) * 32;
        const int k0 = ((idx >> 4) & 15) * 32;
        const int tx = tid & 31, ty = tid >> 5;
        #pragma unroll
        for (int j = 0; j < 4; ++j)
            t[ty + j * 8][tx] = W[(size_t)(k0 + ty + j * 8) * DIM + n0 + tx];
        __syncthreads();
        #pragma unroll
        for (int j = 0; j < 4; ++j) {
            const int nn = ty + j * 8;
            D[(size_t)(n0 + nn) * DIM + k0 + tx] = __float2half(t[tx][nn]);
        }
    } else {
        for (int e = tid; e < 16 * DIM; e += 256) {
            const int j = e >> 9, d = e & 511;
            const float v = (j < 8) ? W_e[d * KEXP + j] : W_s[d * KEXP + j - 8];
            g_wes[e] = __float2half(v);
        }
    }
}

// ---------------------------------------------------------------------------
// Decay helper (2 adjacent d-columns)
// ---------------------------------------------------------------------------
__device__ __forceinline__ void load_decay2(const float* __restrict__ o_param,
                                            int d0, float scale, float o[KEXP][2]) {
    #pragma unroll
    for (int k = 0; k < KEXP; k++) {
        float2 op = *(const float2*)(o_param + k * DIM + d0);
        float ls0 = fminf(op.x, 0.0f) - log1pf(expf(-fabsf(op.x)));
        float ls1 = fminf(op.y, 0.0f) - log1pf(expf(-fabsf(op.y)));
        o[k][0] = expf(ls0 * scale);
        o[k][1] = expf(ls1 * scale);
    }
}

// ---------------------------------------------------------------------------
// Scan phase 1: per-chunk local end state (CHUNK=64).
// 128 threads x 2 d-columns; CTA covers 256 d (grid z splits d).
// e chunk (2KB) staged once; iv via 3-stage cp.async ring (8KB/stage).
// ---------------------------------------------------------------------------
#define SL_TG 8
#define SL_STAGES 3
#define SL_NS (CHUNK/SL_TG)     // 8
#define SL_D 256                // d-columns per CTA

__global__ __launch_bounds__(128) void scan_local_kernel(const float* __restrict__ o_param) {
    __shared__ float es[CHUNK * KEXP];                 // 2 KB
    __shared__ float ivb[SL_STAGES][SL_TG][SL_D];      // 24 KB
    const uint32_t es_u = smem_to_u32(es);
    const uint32_t ivb_u = smem_to_u32(ivb);
    const int c = blockIdx.x, b = blockIdx.y, dz = blockIdx.z;
    const int tid = threadIdx.x;
    const int d0 = dz * SL_D + 2 * tid;

    float o[KEXP][2], m[KEXP][2];
    load_decay2(o_param, d0, INV_TAU, o);
    #pragma unroll
    for (int k = 0; k < KEXP; k++) { m[k][0] = 0.0f; m[k][1] = 0.0f; }

    const size_t rowbase = (size_t)b * SEQ + c * CHUNK;
    const float* ibase = g_i + rowbase * DIM + dz * SL_D;
    const float* ep = g_e + rowbase * KEXP;

    // Prologue group 0: e chunk (2KB = 128 threads x 16B) + iv stage 0
    cp16(es_u + (uint32_t)(tid * 16), ep + tid * 4);
    #pragma unroll
    for (int i = 0; i < 4; ++i) {
        const int q = tid + i * 128;            // 0..511
        const int tl = q >> 6, col = (q & 63) * 4;
        cp16(ivb_u + (uint32_t)((tl * SL_D + col) * 4),
             ibase + (size_t)tl * DIM + col);
    }
    cp_commit();
    // Prologue group 1: iv stage 1
    #pragma unroll
    for (int i = 0; i < 4; ++i) {
        const int q = tid + i * 128;
        const int tl = q >> 6, col = (q & 63) * 4;
        cp16(ivb_u + (uint32_t)(((SL_TG + tl) * SL_D + col) * 4),
             ibase + (size_t)(SL_TG + tl) * DIM + col);
    }
    cp_commit();

    for (int s = 0; s < SL_NS; ++s) {
        cp_wait<SL_STAGES - 2>();
        __syncthreads();

        if (s + SL_STAGES - 1 < SL_NS) {
            const int ns = s + SL_STAGES - 1;
            const int st = ns % SL_STAGES;
            #pragma unroll
            for (int i = 0; i < 4; ++i) {
                const int q = tid + i * 128;
                const int tl = q >> 6, col = (q & 63) * 4;
                cp16(ivb_u + (uint32_t)(((st * SL_TG + tl) * SL_D + col) * 4),
                     ibase + (size_t)(ns * SL_TG + tl) * DIM + col);
            }
        }
        cp_commit();

        const int st = s % SL_STAGES;
        #pragma unroll
        for (int j = 0; j < SL_TG; ++j) {
            const int t = s * SL_TG + j;
            const float2 iv = *(const float2*)(&ivb[st][j][2 * tid]);
            const float4 e0 = *(const float4*)(es + t * KEXP);
            const float4 e1 = *(const float4*)(es + t * KEXP + 4);
            const float ev[KEXP] = {e0.x, e0.y, e0.z, e0.w, e1.x, e1.y, e1.z, e1.w};
            #pragma unroll
            for (int k = 0; k < KEXP; k++) {
                m[k][0] = fmaf(o[k][0], m[k][0], ev[k] * iv.x);
                m[k][1] = fmaf(o[k][1], m[k][1], ev[k] * iv.y);
            }
        }
    }
    #pragma unroll
    for (int k = 0; k < KEXP; k++)
        *(float2*)(g_S + (((size_t)b * NCHUNK + c) * KEXP + k) * DIM + d0) =
            make_float2(m[k][0], m[k][1]);
}

// ---------------------------------------------------------------------------
// Scan phase 2: prefix over 64 chunks; batched register hoists (16-wide MLP).
// ---------------------------------------------------------------------------
#define PFB 16

__global__ __launch_bounds__(DIM) void scan_prefix_kernel(const float* __restrict__ o_param) {
    const int b = blockIdx.x;
    const int kp = blockIdx.y * 2;
    const int d = threadIdx.x;

    float oL0, oL1;
    {
        float op0 = o_param[kp * DIM + d];
        float op1 = o_param[(kp + 1) * DIM + d];
        float ls0 = fminf(op0, 0.0f) - log1pf(expf(-fabsf(op0)));
        float ls1 = fminf(op1, 0.0f) - log1pf(expf(-fabsf(op1)));
        oL0 = expf(ls0 * (INV_TAU * (float)CHUNK));
        oL1 = expf(ls1 * (INV_TAU * (float)CHUNK));
    }

    float p0 = 0.0f, p1 = 0.0f;
    for (int cb = 0; cb < NCHUNK; cb += PFB) {
        float s0[PFB], s1[PFB];
        #pragma unroll
        for (int j = 0; j < PFB; j++) {
            s0[j] = g_S[(((size_t)b * NCHUNK + cb + j) * KEXP + kp) * DIM + d];
            s1[j] = g_S[(((size_t)b * NCHUNK + cb + j) * KEXP + kp + 1) * DIM + d];
        }
        #pragma unroll
        for (int j = 0; j < PFB; j++) {
            g_P[(((size_t)b * NCHUNK + cb + j) * KEXP + kp) * DIM + d] = p0;
            g_P[(((size_t)b * NCHUNK + cb + j) * KEXP + kp + 1) * DIM + d] = p1;
            p0 = fmaf(oL0, p0, s0[j]);
            p1 = fmaf(oL1, p1, s1[j]);
        }
    }
}

// ---------------------------------------------------------------------------
// Scan phase 3 + LayerNorm (CHUNK=64). 256 threads x 2 d-columns.
// Dynamic SMEM: ybuf[16][512] | es[512] | ss[512] | ivb[2][16][512] = 100 KB
// ---------------------------------------------------------------------------
#define TG 16
#define AP_GROUPS (CHUNK/TG)          // 4
#define AP_DYN ((TG*DIM + 2*CHUNK*KEXP + 2*TG*DIM) * 4)   // 102400 B

__global__ __launch_bounds__(256) void scan_apply_ln_kernel(const float* __restrict__ o_param,
                                                            const float* __restrict__ gamma,
                                                            const float* __restrict__ beta) {
    extern __shared__ float dyn[];
    float (*ybuf)[DIM] = (float(*)[DIM])dyn;
    float* es = dyn + TG * DIM;
    float* ss = es + CHUNK * KEXP;
    float* ivb = ss + CHUNK * KEXP;           // [2][TG][DIM]
    const uint32_t es_u = smem_to_u32(es);
    const uint32_t ss_u = smem_to_u32(ss);
    const uint32_t ivb_u = smem_to_u32(ivb);
    __shared__ float smu[TG], srstd[TG];

    const int c = blockIdx.x, b = blockIdx.y;
    const int tid = threadIdx.x;
    const int d0 = 2 * tid;
    const int lane = tid & 31, warp = tid >> 5;   // 8 warps

    float o[KEXP][2], m[KEXP][2];
    load_decay2(o_param, d0, INV_TAU, o);
    #pragma unroll
    for (int k = 0; k < KEXP; k++) {
        float2 p = *(const float2*)(g_P + (((size_t)b * NCHUNK + c) * KEXP + k) * DIM + d0);
        m[k][0] = p.x; m[k][1] = p.y;
    }

    const float2 gam = *(const float2*)(gamma + d0);
    const float2 bet = *(const float2*)(beta + d0);

    const size_t rowbase = (size_t)b * SEQ + c * CHUNK;
    const float* ibase = g_i + rowbase * DIM;
    const float* ep = g_e + rowbase * KEXP;
    const float* sp = g_s + rowbase * KEXP;

    // Prologue: e chunk + s chunk (2KB each = 128 threads x 16B) + iv stage 0
    if (tid < 128) {
        cp16(es_u + (uint32_t)(tid * 16), ep + tid * 4);
        cp16(ss_u + (uint32_t)(tid * 16), sp + tid * 4);
    }
    #pragma unroll
    for (int i = 0; i < 8; ++i) {
        const int q = tid + i * 256;               // 0..2047
        const int tl = q >> 7, col = (q & 127) * 4;
        cp16(ivb_u + (uint32_t)((tl * DIM + col) * 4),
             ibase + (size_t)tl * DIM + col);
    }
    cp_commit();

    for (int g = 0; g < AP_GROUPS; ++g) {
        cp_wait<0>();
        __syncthreads();

        if (g + 1 < AP_GROUPS) {
            const int st = (g + 1) & 1;
            #pragma unroll
            for (int i = 0; i < 8; ++i) {
                const int q = tid + i * 256;
                const int tl = q >> 7, col = (q & 127) * 4;
                cp16(ivb_u + (uint32_t)(((st * TG + tl) * DIM + col) * 4),
                     ibase + (size_t)((g + 1) * TG + tl) * DIM + col);
            }
        }
        cp_commit();

        const float* ivst = ivb + (size_t)(g & 1) * TG * DIM;

        #pragma unroll 4
        for (int tt = 0; tt < TG; ++tt) {
            const int t = g * TG + tt;
            const float2 iv = *(const float2*)(ivst + tt * DIM + d0);
            const float4 e0 = *(const float4*)(es + t * KEXP);
            const float4 e1 = *(const float4*)(es + t * KEXP + 4);
            const float4 s0 = *(const float4*)(ss + t * KEXP);
            const float4 s1 = *(const float4*)(ss + t * KEXP + 4);
            const float ev[KEXP] = {e0.x, e0.y, e0.z, e0.w, e1.x, e1.y, e1.z, e1.w};
            const float sv[KEXP] = {s0.x, s0.y, s0.z, s0.w, s1.x, s1.y, s1.z, s1.w};
            float ya0 = 0.0f, ya1 = 0.0f;
            #pragma unroll
            for (int k = 0; k < KEXP; k++) {
                m[k][0] = fmaf(o[k][0], m[k][0], ev[k] * iv.x);
                m[k][1] = fmaf(o[k][1], m[k][1], ev[k] * iv.y);
                ya0 = fmaf(sv[k], m[k][0], ya0);
                ya1 = fmaf(sv[k], m[k][1], ya1);
            }
            ybuf[tt][d0] = ya0;
            ybuf[tt][d0 + 1] = ya1;
        }
        __syncthreads();

        // 8 warps: warp w reduces timesteps 2w and 2w+1
        #pragma unroll
        for (int h = 0; h < 2; ++h) {
            const int tt = warp * 2 + h;
            float s1r = 0.0f, s2r = 0.0f;
            #pragma unroll
            for (int j = 0; j < 16; ++j) {
                const float v = ybuf[tt][lane + j * 32];
                s1r += v;
                s2r = fmaf(v, v, s2r);
            }
            #pragma unroll
            for (int off = 16; off > 0; off >>= 1) {
                s1r += __shfl_xor_sync(0xFFFFFFFFu, s1r, off);
                s2r += __shfl_xor_sync(0xFFFFFFFFu, s2r, off);
            }
            if (lane == 0) {
                const float mu = s1r * (1.0f / DIM);
                const float var = s2r * (1.0f / DIM) - mu * mu;
                smu[tt] = mu;
                srstd[tt] = rsqrtf(var + LN_EPS);
            }
        }
        __syncthreads();

        #pragma unroll 4
        for (int tt = 0; tt < TG; ++tt) {
            const size_t row = rowbase + g * TG + tt;
            const float rv0 = fmaf((ybuf[tt][d0] - smu[tt]) * srstd[tt], gam.x, bet.x);
            const float rv1 = fmaf((ybuf[tt][d0 + 1] - smu[tt]) * srstd[tt], gam.y, bet.y);
            *(__half2*)(g_yh + row * DIM + d0) = __floats2half2_rn(rv0, rv1);
        }
    }
}

// ---------------------------------------------------------------------------
// Launch
// ---------------------------------------------------------------------------
extern "C" void kernel_launch(void* const* d_in, const int* in_sizes, int n_in,
                              void* d_out, int out_size) {
    const float* x       = (const float*)d_in[0];
    const float* W_i     = (const float*)d_in[1];
    const float* W_e     = (const float*)d_in[2];
    const float* W_s     = (const float*)d_in[3];
    const float* o_param = (const float*)d_in[4];
    const float* gamma   = (const float*)d_in[5];
    const float* beta    = (const float*)d_in[6];
    const float* W_out   = (const float*)d_in[7];
    float* out = (float*)d_out;

    cudaFuncSetAttribute(scan_apply_ln_kernel,
                         cudaFuncAttributeMaxDynamicSharedMemorySize, AP_DYN);

    convert_all_kernel<<<CVT_XBLOCKS + 512 + 1, 256>>>(x, W_i, W_out, W_e, W_s);
    gemm1_kernel<<<dim3(4, 128), 256>>>();
    es_mma_kernel<<<128, 128>>>();
    scan_local_kernel<<<dim3(NCHUNK, BATCH, 2), 128>>>(o_param);
    scan_prefix_kernel<<<dim3(BATCH, KEXP / 2), DIM>>>(o_param);
    scan_apply_ln_kernel<<<dim3(NCHUNK, BATCH), 256, AP_DYN>>>(o_param, gamma, beta);
    gemm2_kernel<<<dim3(4, 128), 256>>>(out);
}

// round 15
// speedup vs baseline: 1.0682x; 1.0682x over previous
#include <cuda_runtime.h>
#include <cuda_fp16.h>
#include <math.h>
#include <cstdint>

// Problem constants
#define BATCH 4
#define SEQ   4096
#define DIM   512
#define KEXP  8
#define ROWS  (BATCH*SEQ)        // 16384 token rows
#define CHUNK 64                 // scan chunk length
#define NCHUNK (SEQ/CHUNK)       // 64 chunks
#define INV_TAU (1.0f/16.0f)
#define LN_EPS 1e-5f

// ---------------------------------------------------------------------------
// Scratch (static device globals)
// ---------------------------------------------------------------------------
__device__ __half g_ih[ROWS * DIM];                     // fp16(x @ W_i)
__device__ float g_e[ROWS * KEXP];
__device__ float g_s[ROWS * KEXP];
__device__ float g_S[BATCH * NCHUNK * KEXP * DIM];
__device__ float g_P[BATCH * NCHUNK * KEXP * DIM];
__device__ __half g_xh[ROWS * DIM];                     // fp16(x)
__device__ __half g_yh[ROWS * DIM];                     // fp16(LN(y))
__device__ __half g_wi[DIM * DIM];                      // W_i^T  [N,K] fp16
__device__ __half g_wo[DIM * DIM];                      // W_out^T [N,K] fp16
__device__ __half g_wes[16 * DIM];                      // [W_e|W_s]^T [16,K] fp16

// ---------------------------------------------------------------------------
// PTX primitives (baseline sm_80+ — legal for compute_103 PTX target)
// ---------------------------------------------------------------------------
__device__ __forceinline__ uint32_t smem_to_u32(const void* p) {
    uint32_t a;
    asm("{ .reg .u64 t; cvta.to.shared.u64 t, %1; cvt.u32.u64 %0, t; }" : "=r"(a) : "l"(p));
    return a;
}

__device__ __forceinline__ void cp16(uint32_t dst, const void* src) {
    asm volatile("cp.async.cg.shared.global [%0], [%1], 16;" :: "r"(dst), "l"(src));
}
__device__ __forceinline__ void cp_commit() {
    asm volatile("cp.async.commit_group;" ::: "memory");
}
template <int N>
__device__ __forceinline__ void cp_wait() {
    asm volatile("cp.async.wait_group %0;" :: "n"(N) : "memory");
}

__device__ __forceinline__ void ldsm4(uint32_t* r, uint32_t addr) {
    asm volatile("ldmatrix.sync.aligned.m8n8.x4.shared.b16 {%0,%1,%2,%3}, [%4];"
                 : "=r"(r[0]), "=r"(r[1]), "=r"(r[2]), "=r"(r[3]) : "r"(addr));
}

__device__ __forceinline__ void mma16816(float* c, const uint32_t* a, const uint32_t* b) {
    asm volatile(
        "mma.sync.aligned.m16n8k16.row.col.f32.f16.f16.f32 "
        "{%0,%1,%2,%3}, {%4,%5,%6,%7}, {%8,%9}, {%0,%1,%2,%3};"
        : "+f"(c[0]), "+f"(c[1]), "+f"(c[2]), "+f"(c[3])
        : "r"(a[0]), "r"(a[1]), "r"(a[2]), "r"(a[3]), "r"(b[0]), "r"(b[1]));
}

// Swizzle: XOR bits[4:5] with bits[7:8], applied to the FINAL 16B-chunk offset.
__device__ __forceinline__ uint32_t swz(uint32_t off) {
    return off ^ (((off >> 7) & 3u) << 4);
}

// ---------------------------------------------------------------------------
// HMMA fp16 GEMM body (templated epilogue: fp16 or fp32 C)
// CTA tile 128x128, 8 warps of 32x64, BK=32, 3-stage ring (48KB).
// ---------------------------------------------------------------------------
#define BK 32
#define NKI (DIM/BK)             // 16 k-iterations
#define GTILE_B 8192             // 128 rows x 64B
#define GSTAGES 3
#define GSM_BYTES (GSTAGES*2*GTILE_B)   // 49152

__device__ __forceinline__ void gemm_load(uint32_t sbase, int stage, int c,
                                          const __half* A, const __half* B,
                                          int row0, int col0, int tid) {
    const int r = tid >> 1;
    const int h = tid & 1;
    const uint32_t so0 = swz((uint32_t)(r * 64 + h * 32));
    const uint32_t so1 = swz((uint32_t)(r * 64 + h * 32 + 16));
    const size_t ga = (size_t)(row0 + r) * DIM + c * BK + h * 16;
    const size_t gb = (size_t)(col0 + r) * DIM + c * BK + h * 16;
    const uint32_t base = sbase + (uint32_t)(stage * 2 * GTILE_B);
    cp16(base + 0 * GTILE_B + so0, A + ga);
    cp16(base + 0 * GTILE_B + so1, A + ga + 8);
    cp16(base + 1 * GTILE_B + so0, B + gb);
    cp16(base + 1 * GTILE_B + so1, B + gb + 8);
}

template <bool HALF_OUT>
__device__ __forceinline__ void gemm_body(char* smem, const __half* __restrict__ A,
                                          const __half* __restrict__ B,
                                          void* __restrict__ Cv,
                                          int row0, int col0) {
    const uint32_t sbase = smem_to_u32(smem);
    const int tid = threadIdx.x;
    const int lane = tid & 31;
    const int wid = tid >> 5;
    const int warp_m = wid >> 1;
    const int warp_n = wid & 1;

    const int lr = lane & 15;
    const int lc = (lane >> 4) & 1;

    float acc[2][8][4];
    #pragma unroll
    for (int m = 0; m < 2; m++)
        #pragma unroll
        for (int n = 0; n < 8; n++)
            #pragma unroll
            for (int q = 0; q < 4; q++) acc[m][n][q] = 0.0f;

    #pragma unroll
    for (int s = 0; s < GSTAGES - 1; ++s) {
        gemm_load(sbase, s, s, A, B, row0, col0, tid);
        cp_commit();
    }

    uint32_t aAddr[2][2], bAddr[4][2];
    #pragma unroll
    for (int m = 0; m < 2; m++)
        #pragma unroll
        for (int kk = 0; kk < 2; kk++)
            aAddr[m][kk] = swz((uint32_t)((warp_m * 32 + m * 16 + lr) * 64
                                          + lc * 16 + kk * 32));
    #pragma unroll
    for (int q = 0; q < 4; q++)
        #pragma unroll
        for (int kk = 0; kk < 2; kk++)
            bAddr[q][kk] = swz((uint32_t)((warp_n * 64 + q * 16 + lr) * 64
                                          + lc * 16 + kk * 32));

    for (int c = 0; c < NKI; ++c) {
        cp_wait<GSTAGES - 2>();
        __syncthreads();

        if (c + GSTAGES - 1 < NKI)
            gemm_load(sbase, (c + GSTAGES - 1) % GSTAGES, c + GSTAGES - 1,
                      A, B, row0, col0, tid);
        cp_commit();

        const uint32_t bb = sbase + (uint32_t)((c % GSTAGES) * 2 * GTILE_B);

        #pragma unroll
        for (int kk = 0; kk < 2; ++kk) {
            uint32_t a[2][4], b[8][2];
            #pragma unroll
            for (int q = 0; q < 4; q++) {
                uint32_t t4[4];
                ldsm4(t4, bb + 1 * GTILE_B + bAddr[q][kk]);
                b[2*q][0] = t4[0]; b[2*q+1][0] = t4[1];
                b[2*q][1] = t4[2]; b[2*q+1][1] = t4[3];
            }
            ldsm4(a[0], bb + aAddr[0][kk]);
            ldsm4(a[1], bb + aAddr[1][kk]);
            #pragma unroll
            for (int m = 0; m < 2; m++)
                #pragma unroll
                for (int n = 0; n < 8; n++) mma16816(acc[m][n], a[m], b[n]);
        }
    }

    const int tr = lane >> 2;
    const int tc = (lane & 3) * 2;
    #pragma unroll
    for (int m = 0; m < 2; m++) {
        const int rbase = row0 + warp_m * 32 + m * 16 + tr;
        #pragma unroll
        for (int n = 0; n < 8; n++) {
            const int col = col0 + warp_n * 64 + n * 8 + tc;
            if (HALF_OUT) {
                __half* C = (__half*)Cv;
                *(__half2*)(C + (size_t)rbase * DIM + col) =
                    __floats2half2_rn(acc[m][n][0], acc[m][n][1]);
                *(__half2*)(C + (size_t)(rbase + 8) * DIM + col) =
                    __floats2half2_rn(acc[m][n][2], acc[m][n][3]);
            } else {
                float* C = (float*)Cv;
                *(float2*)(C + (size_t)rbase * DIM + col) =
                    make_float2(acc[m][n][0], acc[m][n][1]);
                *(float2*)(C + (size_t)(rbase + 8) * DIM + col) =
                    make_float2(acc[m][n][2], acc[m][n][3]);
            }
        }
    }
}

// ---------------------------------------------------------------------------
// es body (fused into gemm1 grid): 256 threads, 8 warps x 16 rows x 16 cols.
// Shares the 48KB smem buffer: abuf 3 x 4KB at 0, W at 12288 (16x520 halves).
// ---------------------------------------------------------------------------
#define ES_PITCH 520
#define ESTAGES 3
#define ENKI 32
#define ES_W_OFF 12288

__device__ __forceinline__ void es_body(char* smem, int row0) {
    const uint32_t ab_u = smem_to_u32(smem);
    __half* w = (__half*)(smem + ES_W_OFF);
    const uint32_t wbase = smem_to_u32(w);
    const int tid = threadIdx.x;
    const int lane = tid & 31;
    const int wid = tid >> 5;            // 0..7

    // Fill W smem: 16 rows x 512 halves, pitch 520
    {
        const int row = tid >> 4;              // 0..15
        const int colb = (tid & 15) * 32;      // 0..480
        #pragma unroll
        for (int q = 0; q < 4; ++q) {
            uint4 v = *(const uint4*)(g_wes + row * DIM + colb + q * 8);
            *(uint4*)(w + row * ES_PITCH + colb + q * 8) = v;
        }
    }

    // A ring: stage = 128 rows x 32B = 4KB; 1 cp16/thread/stage
    const int r = tid >> 1;
    const int h = tid & 1;
    const uint32_t soff = swz((uint32_t)(r * 32 + h * 16));
    #pragma unroll
    for (int s = 0; s < ESTAGES - 1; ++s) {
        cp16(ab_u + (uint32_t)(s * 4096) + soff,
             g_xh + (size_t)(row0 + r) * DIM + s * 16 + h * 8);
        cp_commit();
    }

    const int lr = lane & 15;
    const int lc = (lane >> 4) & 1;
    const uint32_t aAddr = swz((uint32_t)((wid * 16 + lr) * 32 + lc * 16));

    float acc[2][4];
    #pragma unroll
    for (int n = 0; n < 2; n++)
        #pragma unroll
        for (int q = 0; q < 4; q++) acc[n][q] = 0.0f;

    for (int c = 0; c < ENKI; ++c) {
        cp_wait<ESTAGES - 2>();
        __syncthreads();

        if (c + ESTAGES - 1 < ENKI) {
            const int ns = c + ESTAGES - 1;
            cp16(ab_u + (uint32_t)((ns % ESTAGES) * 4096) + soff,
                 g_xh + (size_t)(row0 + r) * DIM + ns * 16 + h * 8);
        }
        cp_commit();

        uint32_t b[2][2];
        #pragma unroll
        for (int nt = 0; nt < 2; ++nt) {
            const uint32_t base = wbase
                + (uint32_t)(((nt * 8 + (lane >> 2)) * ES_PITCH + c * 16 + (lane & 3) * 2) * 2);
            asm volatile("ld.shared.b32 %0, [%1];" : "=r"(b[nt][0]) : "r"(base));
            asm volatile("ld.shared.b32 %0, [%1];" : "=r"(b[nt][1]) : "r"(base + 16));
        }

        uint32_t a[4];
        ldsm4(a, ab_u + (uint32_t)((c % ESTAGES) * 4096) + aAddr);
        mma16816(acc[0], a, b[0]);
        mma16816(acc[1], a, b[1]);
    }

    const int tr = lane >> 2;
    const int tc = (lane & 3) * 2;
    const int rbase = row0 + wid * 16 + tr;
    #pragma unroll
    for (int nt = 0; nt < 2; nt++) {
        float* dst = nt ? g_s : g_e;
        *(float2*)(dst + (size_t)rbase * KEXP + tc) = make_float2(acc[nt][0], acc[nt][1]);
        *(float2*)(dst + (size_t)(rbase + 8) * KEXP + tc) = make_float2(acc[nt][2], acc[nt][3]);
    }
}

// Fused gemm1 + es: grid (5, 128). bx<4 = gemm tiles, bx==4 = es tile.
__global__ __launch_bounds__(256, 2) void gemm1_es_kernel() {
    __shared__ __align__(128) char smbuf[GSM_BYTES];
    if (blockIdx.x < 4)
        gemm_body<true>(smbuf, g_xh, g_wi, g_ih, blockIdx.y * 128, blockIdx.x * 128);
    else
        es_body(smbuf, blockIdx.y * 128);
}

__global__ __launch_bounds__(256, 2) void gemm2_kernel(float* __restrict__ out) {
    __shared__ __align__(128) char smbuf[GSM_BYTES];
    gemm_body<false>(smbuf, g_yh, g_wo, out, blockIdx.y * 128, blockIdx.x * 128);
}

// ---------------------------------------------------------------------------
// Fused conversions (unchanged)
// ---------------------------------------------------------------------------
#define CVT_XBLOCKS (ROWS * DIM / 4 / 256)   // 8192

__global__ __launch_bounds__(256) void convert_all_kernel(
        const float* __restrict__ x,
        const float* __restrict__ W_i, const float* __restrict__ W_out,
        const float* __restrict__ W_e, const float* __restrict__ W_s) {
    __shared__ float t[32][33];
    const int bid = blockIdx.x;
    const int tid = threadIdx.x;

    if (bid < CVT_XBLOCKS) {
        const size_t i = (size_t)bid * 256 + tid;
        float4 v = ((const float4*)x)[i];
        __half h[4];
        h[0] = __float2half(v.x);
        h[1] = __float2half(v.y);
        h[2] = __float2half(v.z);
        h[3] = __float2half(v.w);
        ((uint2*)g_xh)[i] = *(uint2*)h;
    } else if (bid < CVT_XBLOCKS + 512) {
        const int idx = bid - CVT_XBLOCKS;
        const int z = idx >> 8;
        const float* W = z ? W_out : W_i;
        __half* D = z ? g_wo : g_wi;
        const int n0 = (idx & 15) * 32;
        const int k0 = ((idx >> 4) & 15) * 32;
        const int tx = tid & 31, ty = tid >> 5;
        #pragma unroll
        for (int j = 0; j < 4; ++j)
            t[ty + j * 8][tx] = W[(size_t)(k0 + ty + j * 8) * DIM + n0 + tx];
        __syncthreads();
        #pragma unroll
        for (int j = 0; j < 4; ++j) {
            const int nn = ty + j * 8;
            D[(size_t)(n0 + nn) * DIM + k0 + tx] = __float2half(t[tx][nn]);
        }
    } else {
        for (int e = tid; e < 16 * DIM; e += 256) {
            const int j = e >> 9, d = e & 511;
            const float v = (j < 8) ? W_e[d * KEXP + j] : W_s[d * KEXP + j - 8];
            g_wes[e] = __float2half(v);
        }
    }
}

// ---------------------------------------------------------------------------
// Decay helper (2 adjacent d-columns)
// ---------------------------------------------------------------------------
__device__ __forceinline__ void load_decay2(const float* __restrict__ o_param,
                                            int d0, float scale, float o[KEXP][2]) {
    #pragma unroll
    for (int k = 0; k < KEXP; k++) {
        float2 op = *(const float2*)(o_param + k * DIM + d0);
        float ls0 = fminf(op.x, 0.0f) - log1pf(expf(-fabsf(op.x)));
        float ls1 = fminf(op.y, 0.0f) - log1pf(expf(-fabsf(op.y)));
        o[k][0] = expf(ls0 * scale);
        o[k][1] = expf(ls1 * scale);
    }
}

// ---------------------------------------------------------------------------
// Scan phase 1: per-chunk local end state (CHUNK=64, fp16 iv).
// 128 threads x 2 d-columns; CTA covers 256 d (grid z splits d).
// ---------------------------------------------------------------------------
#define SL_TG 8
#define SL_STAGES 3
#define SL_NS (CHUNK/SL_TG)     // 8
#define SL_D 256

__global__ __launch_bounds__(128) void scan_local_kernel(const float* __restrict__ o_param) {
    __shared__ float es[CHUNK * KEXP];                 // 2 KB
    __shared__ __half ivb[SL_STAGES][SL_TG][SL_D];     // 12 KB
    const uint32_t es_u = smem_to_u32(es);
    const uint32_t ivb_u = smem_to_u32(ivb);
    const int c = blockIdx.x, b = blockIdx.y, dz = blockIdx.z;
    const int tid = threadIdx.x;
    const int d0 = dz * SL_D + 2 * tid;

    float o[KEXP][2], m[KEXP][2];
    load_decay2(o_param, d0, INV_TAU, o);
    #pragma unroll
    for (int k = 0; k < KEXP; k++) { m[k][0] = 0.0f; m[k][1] = 0.0f; }

    const size_t rowbase = (size_t)b * SEQ + c * CHUNK;
    const __half* ibase = g_ih + rowbase * DIM + dz * SL_D;
    const float* ep = g_e + rowbase * KEXP;

    // Prologue group 0: e chunk + iv stage 0 (2 cp16/thread: 8x256 halves)
    cp16(es_u + (uint32_t)(tid * 16), ep + tid * 4);
    #pragma unroll
    for (int i = 0; i < 2; ++i) {
        const int q = tid + i * 128;            // 0..255
        const int tl = q >> 5, col = (q & 31) * 8;
        cp16(ivb_u + (uint32_t)((tl * SL_D + col) * 2),
             ibase + (size_t)tl * DIM + col);
    }
    cp_commit();
    // Prologue group 1: iv stage 1
    #pragma unroll
    for (int i = 0; i < 2; ++i) {
        const int q = tid + i * 128;
        const int tl = q >> 5, col = (q & 31) * 8;
        cp16(ivb_u + (uint32_t)(((SL_TG + tl) * SL_D + col) * 2),
             ibase + (size_t)(SL_TG + tl) * DIM + col);
    }
    cp_commit();

    for (int s = 0; s < SL_NS; ++s) {
        cp_wait<SL_STAGES - 2>();
        __syncthreads();

        if (s + SL_STAGES - 1 < SL_NS) {
            const int ns = s + SL_STAGES - 1;
            const int st = ns % SL_STAGES;
            #pragma unroll
            for (int i = 0; i < 2; ++i) {
                const int q = tid + i * 128;
                const int tl = q >> 5, col = (q & 31) * 8;
                cp16(ivb_u + (uint32_t)(((st * SL_TG + tl) * SL_D + col) * 2),
                     ibase + (size_t)(ns * SL_TG + tl) * DIM + col);
            }
        }
        cp_commit();

        const int st = s % SL_STAGES;
        #pragma unroll
        for (int j = 0; j < SL_TG; ++j) {
            const int t = s * SL_TG + j;
            const float2 iv = __half22float2(*(const __half2*)(&ivb[st][j][2 * tid]));
            const float4 e0 = *(const float4*)(es + t * KEXP);
            const float4 e1 = *(const float4*)(es + t * KEXP + 4);
            const float ev[KEXP] = {e0.x, e0.y, e0.z, e0.w, e1.x, e1.y, e1.z, e1.w};
            #pragma unroll
            for (int k = 0; k < KEXP; k++) {
                m[k][0] = fmaf(o[k][0], m[k][0], ev[k] * iv.x);
                m[k][1] = fmaf(o[k][1], m[k][1], ev[k] * iv.y);
            }
        }
    }
    #pragma unroll
    for (int k = 0; k < KEXP; k++)
        *(float2*)(g_S + (((size_t)b * NCHUNK + c) * KEXP + k) * DIM + d0) =
            make_float2(m[k][0], m[k][1]);
}

// ---------------------------------------------------------------------------
// Scan phase 2: prefix over 64 chunks; batched register hoists.
// ---------------------------------------------------------------------------
#define PFB 16

__global__ __launch_bounds__(DIM) void scan_prefix_kernel(const float* __restrict__ o_param) {
    const int b = blockIdx.x;
    const int kp = blockIdx.y * 2;
    const int d = threadIdx.x;

    float oL0, oL1;
    {
        float op0 = o_param[kp * DIM + d];
        float op1 = o_param[(kp + 1) * DIM + d];
        float ls0 = fminf(op0, 0.0f) - log1pf(expf(-fabsf(op0)));
        float ls1 = fminf(op1, 0.0f) - log1pf(expf(-fabsf(op1)));
        oL0 = expf(ls0 * (INV_TAU * (float)CHUNK));
        oL1 = expf(ls1 * (INV_TAU * (float)CHUNK));
    }

    float p0 = 0.0f, p1 = 0.0f;
    for (int cb = 0; cb < NCHUNK; cb += PFB) {
        float s0[PFB], s1[PFB];
        #pragma unroll
        for (int j = 0; j < PFB; j++) {
            s0[j] = g_S[(((size_t)b * NCHUNK + cb + j) * KEXP + kp) * DIM + d];
            s1[j] = g_S[(((size_t)b * NCHUNK + cb + j) * KEXP + kp + 1) * DIM + d];
        }
        #pragma unroll
        for (int j = 0; j < PFB; j++) {
            g_P[(((size_t)b * NCHUNK + cb + j) * KEXP + kp) * DIM + d] = p0;
            g_P[(((size_t)b * NCHUNK + cb + j) * KEXP + kp + 1) * DIM + d] = p1;
            p0 = fmaf(oL0, p0, s0[j]);
            p1 = fmaf(oL1, p1, s1[j]);
        }
    }
}

// ---------------------------------------------------------------------------
// Scan phase 3 + LayerNorm (CHUNK=64, fp16 iv). 256 threads x 2 d-columns.
// Dynamic SMEM: ybuf[16][512] f32 | es[512] | ss[512] | ivh[2][16][512] fp16
//   = 32768 + 2048 + 2048 + 32768 = 69632 B
// ---------------------------------------------------------------------------
#define TG 16
#define AP_GROUPS (CHUNK/TG)          // 4
#define AP_DYN 69632

__global__ __launch_bounds__(256) void scan_apply_ln_kernel(const float* __restrict__ o_param,
                                                            const float* __restrict__ gamma,
                                                            const float* __restrict__ beta) {
    extern __shared__ float dyn[];
    float (*ybuf)[DIM] = (float(*)[DIM])dyn;
    float* es = dyn + TG * DIM;
    float* ss = es + CHUNK * KEXP;
    __half* ivh = (__half*)(ss + CHUNK * KEXP);   // [2][TG][DIM]
    const uint32_t es_u = smem_to_u32(es);
    const uint32_t ss_u = smem_to_u32(ss);
    const uint32_t ivh_u = smem_to_u32(ivh);
    __shared__ float smu[TG], srstd[TG];

    const int c = blockIdx.x, b = blockIdx.y;
    const int tid = threadIdx.x;
    const int d0 = 2 * tid;
    const int lane = tid & 31, warp = tid >> 5;   // 8 warps

    float o[KEXP][2], m[KEXP][2];
    load_decay2(o_param, d0, INV_TAU, o);
    #pragma unroll
    for (int k = 0; k < KEXP; k++) {
        float2 p = *(const float2*)(g_P + (((size_t)b * NCHUNK + c) * KEXP + k) * DIM + d0);
        m[k][0] = p.x; m[k][1] = p.y;
    }

    const float2 gam = *(const float2*)(gamma + d0);
    const float2 bet = *(const float2*)(beta + d0);

    const size_t rowbase = (size_t)b * SEQ + c * CHUNK;
    const __half* ibase = g_ih + rowbase * DIM;
    const float* ep = g_e + rowbase * KEXP;
    const float* sp = g_s + rowbase * KEXP;

    // Prologue: e chunk + s chunk (2KB each) + iv stage 0 (16x512 halves)
    if (tid < 128)
        cp16(es_u + (uint32_t)(tid * 16), ep + tid * 4);
    else
        cp16(ss_u + (uint32_t)((tid - 128) * 16), sp + (tid - 128) * 4);
    #pragma unroll
    for (int i = 0; i < 4; ++i) {
        const int q = tid + i * 256;               // 0..1023
        const int tl = q >> 6, col = (q & 63) * 8;
        cp16(ivh_u + (uint32_t)((tl * DIM + col) * 2),
             ibase + (size_t)tl * DIM + col);
    }
    cp_commit();

    for (int g = 0; g < AP_GROUPS; ++g) {
        cp_wait<0>();
        __syncthreads();

        if (g + 1 < AP_GROUPS) {
            const int st = (g + 1) & 1;
            #pragma unroll
            for (int i = 0; i < 4; ++i) {
                const int q = tid + i * 256;
                const int tl = q >> 6, col = (q & 63) * 8;
                cp16(ivh_u + (uint32_t)(((st * TG + tl) * DIM + col) * 2),
                     ibase + (size_t)((g + 1) * TG + tl) * DIM + col);
            }
        }
        cp_commit();

        const __half* ivst = ivh + (size_t)(g & 1) * TG * DIM;

        #pragma unroll 4
        for (int tt = 0; tt < TG; ++tt) {
            const int t = g * TG + tt;
            const float2 iv = __half22float2(*(const __half2*)(ivst + tt * DIM + d0));
            const float4 e0 = *(const float4*)(es + t * KEXP);
            const float4 e1 = *(const float4*)(es + t * KEXP + 4);
            const float4 s0 = *(const float4*)(ss + t * KEXP);
            const float4 s1 = *(const float4*)(ss + t * KEXP + 4);
            const float ev[KEXP] = {e0.x, e0.y, e0.z, e0.w, e1.x, e1.y, e1.z, e1.w};
            const float sv[KEXP] = {s0.x, s0.y, s0.z, s0.w, s1.x, s1.y, s1.z, s1.w};
            float ya0 = 0.0f, ya1 = 0.0f;
            #pragma unroll
            for (int k = 0; k < KEXP; k++) {
                m[k][0] = fmaf(o[k][0], m[k][0], ev[k] * iv.x);
                m[k][1] = fmaf(o[k][1], m[k][1], ev[k] * iv.y);
                ya0 = fmaf(sv[k], m[k][0], ya0);
                ya1 = fmaf(sv[k], m[k][1], ya1);
            }
            ybuf[tt][d0] = ya0;
            ybuf[tt][d0 + 1] = ya1;
        }
        __syncthreads();

        // 8 warps: warp w reduces timesteps 2w and 2w+1
        #pragma unroll
        for (int h = 0; h < 2; ++h) {
            const int tt = warp * 2 + h;
            float s1r = 0.0f, s2r = 0.0f;
            #pragma unroll
            for (int j = 0; j < 16; ++j) {
                const float v = ybuf[tt][lane + j * 32];
                s1r += v;
                s2r = fmaf(v, v, s2r);
            }
            #pragma unroll
            for (int off = 16; off > 0; off >>= 1) {
                s1r += __shfl_xor_sync(0xFFFFFFFFu, s1r, off);
                s2r += __shfl_xor_sync(0xFFFFFFFFu, s2r, off);
            }
            if (lane == 0) {
                const float mu = s1r * (1.0f / DIM);
                const float var = s2r * (1.0f / DIM) - mu * mu;
                smu[tt] = mu;
                srstd[tt] = rsqrtf(var + LN_EPS);
            }
        }
        __syncthreads();

        #pragma unroll 4
        for (int tt = 0; tt < TG; ++tt) {
            const size_t row = rowbase + g * TG + tt;
            const float rv0 = fmaf((ybuf[tt][d0] - smu[tt]) * srstd[tt], gam.x, bet.x);
            const float rv1 = fmaf((ybuf[tt][d0 + 1] - smu[tt]) * srstd[tt], gam.y, bet.y);
            *(__half2*)(g_yh + row * DIM + d0) = __floats2half2_rn(rv0, rv1);
        }
    }
}

// ---------------------------------------------------------------------------
// Launch
// ---------------------------------------------------------------------------
extern "C" void kernel_launch(void* const* d_in, const int* in_sizes, int n_in,
                              void* d_out, int out_size) {
    const float* x       = (const float*)d_in[0];
    const float* W_i     = (const float*)d_in[1];
    const float* W_e     = (const float*)d_in[2];
    const float* W_s     = (const float*)d_in[3];
    const float* o_param = (const float*)d_in[4];
    const float* gamma   = (const float*)d_in[5];
    const float* beta    = (const float*)d_in[6];
    const float* W_out   = (const float*)d_in[7];
    float* out = (float*)d_out;

    cudaFuncSetAttribute(scan_apply_ln_kernel,
                         cudaFuncAttributeMaxDynamicSharedMemorySize, AP_DYN);

    convert_all_kernel<<<CVT_XBLOCKS + 512 + 1, 256>>>(x, W_i, W_out, W_e, W_s);
    gemm1_es_kernel<<<dim3(5, 128), 256>>>();
    scan_local_kernel<<<dim3(NCHUNK, BATCH, 2), 128>>>(o_param);
    scan_prefix_kernel<<<dim3(BATCH, KEXP / 2), DIM>>>(o_param);
    scan_apply_ln_kernel<<<dim3(NCHUNK, BATCH), 256, AP_DYN>>>(o_param, gamma, beta);
    gemm2_kernel<<<dim3(4, 128), 256>>>(out);
}

// round 16
// speedup vs baseline: 1.1022x; 1.0319x over previous
#include <cuda_runtime.h>
#include <cuda_fp16.h>
#include <math.h>
#include <cstdint>

// Problem constants
#define BATCH 4
#define SEQ   4096
#define DIM   512
#define KEXP  8
#define ROWS  (BATCH*SEQ)        // 16384 token rows
#define CHUNK 64                 // scan chunk length
#define NCHUNK (SEQ/CHUNK)       // 64 chunks
#define INV_TAU (1.0f/16.0f)
#define LN_EPS 1e-5f

// ---------------------------------------------------------------------------
// Scratch (static device globals)
// ---------------------------------------------------------------------------
__device__ __half g_ih[ROWS * DIM];                     // fp16(x @ W_i)
__device__ float g_e[ROWS * KEXP];
__device__ float g_s[ROWS * KEXP];
__device__ float g_S[BATCH * NCHUNK * KEXP * DIM];
__device__ float g_P[BATCH * NCHUNK * KEXP * DIM];
__device__ __half g_xh[ROWS * DIM];                     // fp16(x)
__device__ __half g_yh[ROWS * DIM];                     // fp16(LN(y))
__device__ __half g_wi[DIM * DIM];                      // W_i^T  [N,K] fp16
__device__ __half g_wo[DIM * DIM];                      // W_out^T [N,K] fp16
__device__ __half g_wes[16 * DIM];                      // [W_e|W_s]^T [16,K] fp16

// ---------------------------------------------------------------------------
// PTX primitives (baseline sm_80+ — legal for compute_103 PTX target)
// ---------------------------------------------------------------------------
__device__ __forceinline__ uint32_t smem_to_u32(const void* p) {
    uint32_t a;
    asm("{ .reg .u64 t; cvta.to.shared.u64 t, %1; cvt.u32.u64 %0, t; }" : "=r"(a) : "l"(p));
    return a;
}

__device__ __forceinline__ void cp16(uint32_t dst, const void* src) {
    asm volatile("cp.async.cg.shared.global [%0], [%1], 16;" :: "r"(dst), "l"(src));
}
__device__ __forceinline__ void cp_commit() {
    asm volatile("cp.async.commit_group;" ::: "memory");
}
template <int N>
__device__ __forceinline__ void cp_wait() {
    asm volatile("cp.async.wait_group %0;" :: "n"(N) : "memory");
}

__device__ __forceinline__ void ldsm4(uint32_t* r, uint32_t addr) {
    asm volatile("ldmatrix.sync.aligned.m8n8.x4.shared.b16 {%0,%1,%2,%3}, [%4];"
                 : "=r"(r[0]), "=r"(r[1]), "=r"(r[2]), "=r"(r[3]) : "r"(addr));
}

__device__ __forceinline__ void mma16816(float* c, const uint32_t* a, const uint32_t* b) {
    asm volatile(
        "mma.sync.aligned.m16n8k16.row.col.f32.f16.f16.f32 "
        "{%0,%1,%2,%3}, {%4,%5,%6,%7}, {%8,%9}, {%0,%1,%2,%3};"
        : "+f"(c[0]), "+f"(c[1]), "+f"(c[2]), "+f"(c[3])
        : "r"(a[0]), "r"(a[1]), "r"(a[2]), "r"(a[3]), "r"(b[0]), "r"(b[1]));
}

// Swizzle: XOR bits[4:5] with bits[7:8], applied to the FINAL 16B-chunk offset.
__device__ __forceinline__ uint32_t swz(uint32_t off) {
    return off ^ (((off >> 7) & 3u) << 4);
}

// ---------------------------------------------------------------------------
// HMMA fp16 GEMM body (templated epilogue: fp16 or fp32 C)
// CTA tile 128x128, 8 warps of 32x64, BK=32, 3-stage ring (48KB).
// ---------------------------------------------------------------------------
#define BK 32
#define NKI (DIM/BK)             // 16 k-iterations
#define GTILE_B 8192             // 128 rows x 64B
#define GSTAGES 3
#define GSM_BYTES (GSTAGES*2*GTILE_B)   // 49152

__device__ __forceinline__ void gemm_load(uint32_t sbase, int stage, int c,
                                          const __half* A, const __half* B,
                                          int row0, int col0, int tid) {
    const int r = tid >> 1;
    const int h = tid & 1;
    const uint32_t so0 = swz((uint32_t)(r * 64 + h * 32));
    const uint32_t so1 = swz((uint32_t)(r * 64 + h * 32 + 16));
    const size_t ga = (size_t)(row0 + r) * DIM + c * BK + h * 16;
    const size_t gb = (size_t)(col0 + r) * DIM + c * BK + h * 16;
    const uint32_t base = sbase + (uint32_t)(stage * 2 * GTILE_B);
    cp16(base + 0 * GTILE_B + so0, A + ga);
    cp16(base + 0 * GTILE_B + so1, A + ga + 8);
    cp16(base + 1 * GTILE_B + so0, B + gb);
    cp16(base + 1 * GTILE_B + so1, B + gb + 8);
}

template <bool HALF_OUT>
__device__ __forceinline__ void gemm_body(char* smem, const __half* __restrict__ A,
                                          const __half* __restrict__ B,
                                          void* __restrict__ Cv,
                                          int row0, int col0) {
    const uint32_t sbase = smem_to_u32(smem);
    const int tid = threadIdx.x;
    const int lane = tid & 31;
    const int wid = tid >> 5;
    const int warp_m = wid >> 1;
    const int warp_n = wid & 1;

    const int lr = lane & 15;
    const int lc = (lane >> 4) & 1;

    float acc[2][8][4];
    #pragma unroll
    for (int m = 0; m < 2; m++)
        #pragma unroll
        for (int n = 0; n < 8; n++)
            #pragma unroll
            for (int q = 0; q < 4; q++) acc[m][n][q] = 0.0f;

    #pragma unroll
    for (int s = 0; s < GSTAGES - 1; ++s) {
        gemm_load(sbase, s, s, A, B, row0, col0, tid);
        cp_commit();
    }

    uint32_t aAddr[2][2], bAddr[4][2];
    #pragma unroll
    for (int m = 0; m < 2; m++)
        #pragma unroll
        for (int kk = 0; kk < 2; kk++)
            aAddr[m][kk] = swz((uint32_t)((warp_m * 32 + m * 16 + lr) * 64
                                          + lc * 16 + kk * 32));
    #pragma unroll
    for (int q = 0; q < 4; q++)
        #pragma unroll
        for (int kk = 0; kk < 2; kk++)
            bAddr[q][kk] = swz((uint32_t)((warp_n * 64 + q * 16 + lr) * 64
                                          + lc * 16 + kk * 32));

    for (int c = 0; c < NKI; ++c) {
        cp_wait<GSTAGES - 2>();
        __syncthreads();

        if (c + GSTAGES - 1 < NKI)
            gemm_load(sbase, (c + GSTAGES - 1) % GSTAGES, c + GSTAGES - 1,
                      A, B, row0, col0, tid);
        cp_commit();

        const uint32_t bb = sbase + (uint32_t)((c % GSTAGES) * 2 * GTILE_B);

        #pragma unroll
        for (int kk = 0; kk < 2; ++kk) {
            uint32_t a[2][4], b[8][2];
            #pragma unroll
            for (int q = 0; q < 4; q++) {
                uint32_t t4[4];
                ldsm4(t4, bb + 1 * GTILE_B + bAddr[q][kk]);
                b[2*q][0] = t4[0]; b[2*q+1][0] = t4[1];
                b[2*q][1] = t4[2]; b[2*q+1][1] = t4[3];
            }
            ldsm4(a[0], bb + aAddr[0][kk]);
            ldsm4(a[1], bb + aAddr[1][kk]);
            #pragma unroll
            for (int m = 0; m < 2; m++)
                #pragma unroll
                for (int n = 0; n < 8; n++) mma16816(acc[m][n], a[m], b[n]);
        }
    }

    const int tr = lane >> 2;
    const int tc = (lane & 3) * 2;
    #pragma unroll
    for (int m = 0; m < 2; m++) {
        const int rbase = row0 + warp_m * 32 + m * 16 + tr;
        #pragma unroll
        for (int n = 0; n < 8; n++) {
            const int col = col0 + warp_n * 64 + n * 8 + tc;
            if (HALF_OUT) {
                __half* C = (__half*)Cv;
                *(__half2*)(C + (size_t)rbase * DIM + col) =
                    __floats2half2_rn(acc[m][n][0], acc[m][n][1]);
                *(__half2*)(C + (size_t)(rbase + 8) * DIM + col) =
                    __floats2half2_rn(acc[m][n][2], acc[m][n][3]);
            } else {
                float* C = (float*)Cv;
                *(float2*)(C + (size_t)rbase * DIM + col) =
                    make_float2(acc[m][n][0], acc[m][n][1]);
                *(float2*)(C + (size_t)(rbase + 8) * DIM + col) =
                    make_float2(acc[m][n][2], acc[m][n][3]);
            }
        }
    }
}

// ---------------------------------------------------------------------------
// es body (fused into gemm1 grid): 256 threads, 8 warps x 16 rows x 16 cols.
// Shares the 48KB smem buffer: abuf 3 x 4KB at 0, W at 12288 (16x520 halves).
// ---------------------------------------------------------------------------
#define ES_PITCH 520
#define ESTAGES 3
#define ENKI 32
#define ES_W_OFF 12288

__device__ __forceinline__ void es_body(char* smem, int row0) {
    const uint32_t ab_u = smem_to_u32(smem);
    __half* w = (__half*)(smem + ES_W_OFF);
    const uint32_t wbase = smem_to_u32(w);
    const int tid = threadIdx.x;
    const int lane = tid & 31;
    const int wid = tid >> 5;            // 0..7

    // Fill W smem: 16 rows x 512 halves, pitch 520
    {
        const int row = tid >> 4;              // 0..15
        const int colb = (tid & 15) * 32;      // 0..480
        #pragma unroll
        for (int q = 0; q < 4; ++q) {
            uint4 v = *(const uint4*)(g_wes + row * DIM + colb + q * 8);
            *(uint4*)(w + row * ES_PITCH + colb + q * 8) = v;
        }
    }

    // A ring: stage = 128 rows x 32B = 4KB; 1 cp16/thread/stage
    const int r = tid >> 1;
    const int h = tid & 1;
    const uint32_t soff = swz((uint32_t)(r * 32 + h * 16));
    #pragma unroll
    for (int s = 0; s < ESTAGES - 1; ++s) {
        cp16(ab_u + (uint32_t)(s * 4096) + soff,
             g_xh + (size_t)(row0 + r) * DIM + s * 16 + h * 8);
        cp_commit();
    }

    const int lr = lane & 15;
    const int lc = (lane >> 4) & 1;
    const uint32_t aAddr = swz((uint32_t)((wid * 16 + lr) * 32 + lc * 16));

    float acc[2][4];
    #pragma unroll
    for (int n = 0; n < 2; n++)
        #pragma unroll
        for (int q = 0; q < 4; q++) acc[n][q] = 0.0f;

    for (int c = 0; c < ENKI; ++c) {
        cp_wait<ESTAGES - 2>();
        __syncthreads();

        if (c + ESTAGES - 1 < ENKI) {
            const int ns = c + ESTAGES - 1;
            cp16(ab_u + (uint32_t)((ns % ESTAGES) * 4096) + soff,
                 g_xh + (size_t)(row0 + r) * DIM + ns * 16 + h * 8);
        }
        cp_commit();

        uint32_t b[2][2];
        #pragma unroll
        for (int nt = 0; nt < 2; ++nt) {
            const uint32_t base = wbase
                + (uint32_t)(((nt * 8 + (lane >> 2)) * ES_PITCH + c * 16 + (lane & 3) * 2) * 2);
            asm volatile("ld.shared.b32 %0, [%1];" : "=r"(b[nt][0]) : "r"(base));
            asm volatile("ld.shared.b32 %0, [%1];" : "=r"(b[nt][1]) : "r"(base + 16));
        }

        uint32_t a[4];
        ldsm4(a, ab_u + (uint32_t)((c % ESTAGES) * 4096) + aAddr);
        mma16816(acc[0], a, b[0]);
        mma16816(acc[1], a, b[1]);
    }

    const int tr = lane >> 2;
    const int tc = (lane & 3) * 2;
    const int rbase = row0 + wid * 16 + tr;
    #pragma unroll
    for (int nt = 0; nt < 2; nt++) {
        float* dst = nt ? g_s : g_e;
        *(float2*)(dst + (size_t)rbase * KEXP + tc) = make_float2(acc[nt][0], acc[nt][1]);
        *(float2*)(dst + (size_t)(rbase + 8) * KEXP + tc) = make_float2(acc[nt][2], acc[nt][3]);
    }
}

// Fused gemm1 + es: grid (5, 128). bx<4 = gemm tiles, bx==4 = es tile.
__global__ __launch_bounds__(256, 2) void gemm1_es_kernel() {
    __shared__ __align__(128) char smbuf[GSM_BYTES];
    if (blockIdx.x < 4)
        gemm_body<true>(smbuf, g_xh, g_wi, g_ih, blockIdx.y * 128, blockIdx.x * 128);
    else
        es_body(smbuf, blockIdx.y * 128);
}

__global__ __launch_bounds__(256, 2) void gemm2_kernel(float* __restrict__ out) {
    __shared__ __align__(128) char smbuf[GSM_BYTES];
    gemm_body<false>(smbuf, g_yh, g_wo, out, blockIdx.y * 128, blockIdx.x * 128);
}

// ---------------------------------------------------------------------------
// Fused conversions (unchanged)
// ---------------------------------------------------------------------------
#define CVT_XBLOCKS (ROWS * DIM / 4 / 256)   // 8192

__global__ __launch_bounds__(256) void convert_all_kernel(
        const float* __restrict__ x,
        const float* __restrict__ W_i, const float* __restrict__ W_out,
        const float* __restrict__ W_e, const float* __restrict__ W_s) {
    __shared__ float t[32][33];
    const int bid = blockIdx.x;
    const int tid = threadIdx.x;

    if (bid < CVT_XBLOCKS) {
        const size_t i = (size_t)bid * 256 + tid;
        float4 v = ((const float4*)x)[i];
        __half h[4];
        h[0] = __float2half(v.x);
        h[1] = __float2half(v.y);
        h[2] = __float2half(v.z);
        h[3] = __float2half(v.w);
        ((uint2*)g_xh)[i] = *(uint2*)h;
    } else if (bid < CVT_XBLOCKS + 512) {
        const int idx = bid - CVT_XBLOCKS;
        const int z = idx >> 8;
        const float* W = z ? W_out : W_i;
        __half* D = z ? g_wo : g_wi;
        const int n0 = (idx & 15) * 32;
        const int k0 = ((idx >> 4) & 15) * 32;
        const int tx = tid & 31, ty = tid >> 5;
        #pragma unroll
        for (int j = 0; j < 4; ++j)
            t[ty + j * 8][tx] = W[(size_t)(k0 + ty + j * 8) * DIM + n0 + tx];
        __syncthreads();
        #pragma unroll
        for (int j = 0; j < 4; ++j) {
            const int nn = ty + j * 8;
            D[(size_t)(n0 + nn) * DIM + k0 + tx] = __float2half(t[tx][nn]);
        }
    } else {
        for (int e = tid; e < 16 * DIM; e += 256) {
            const int j = e >> 9, d = e & 511;
            const float v = (j < 8) ? W_e[d * KEXP + j] : W_s[d * KEXP + j - 8];
            g_wes[e] = __float2half(v);
        }
    }
}

// ---------------------------------------------------------------------------
// Decay helper (2 adjacent d-columns)
// ---------------------------------------------------------------------------
__device__ __forceinline__ void load_decay2(const float* __restrict__ o_param,
                                            int d0, float scale, float o[KEXP][2]) {
    #pragma unroll
    for (int k = 0; k < KEXP; k++) {
        float2 op = *(const float2*)(o_param + k * DIM + d0);
        float ls0 = fminf(op.x, 0.0f) - log1pf(expf(-fabsf(op.x)));
        float ls1 = fminf(op.y, 0.0f) - log1pf(expf(-fabsf(op.y)));
        o[k][0] = expf(ls0 * scale);
        o[k][1] = expf(ls1 * scale);
    }
}

// ---------------------------------------------------------------------------
// Scan phase 1: per-chunk local end state (CHUNK=64, fp16 iv).
// 128 threads x 2 d-columns; CTA covers 256 d (grid z splits d).
// ---------------------------------------------------------------------------
#define SL_TG 8
#define SL_STAGES 3
#define SL_NS (CHUNK/SL_TG)     // 8
#define SL_D 256

__global__ __launch_bounds__(128) void scan_local_kernel(const float* __restrict__ o_param) {
    __shared__ float es[CHUNK * KEXP];                 // 2 KB
    __shared__ __half ivb[SL_STAGES][SL_TG][SL_D];     // 12 KB
    const uint32_t es_u = smem_to_u32(es);
    const uint32_t ivb_u = smem_to_u32(ivb);
    const int c = blockIdx.x, b = blockIdx.y, dz = blockIdx.z;
    const int tid = threadIdx.x;
    const int d0 = dz * SL_D + 2 * tid;

    float o[KEXP][2], m[KEXP][2];
    load_decay2(o_param, d0, INV_TAU, o);
    #pragma unroll
    for (int k = 0; k < KEXP; k++) { m[k][0] = 0.0f; m[k][1] = 0.0f; }

    const size_t rowbase = (size_t)b * SEQ + c * CHUNK;
    const __half* ibase = g_ih + rowbase * DIM + dz * SL_D;
    const float* ep = g_e + rowbase * KEXP;

    // Prologue group 0: e chunk + iv stage 0 (2 cp16/thread: 8x256 halves)
    cp16(es_u + (uint32_t)(tid * 16), ep + tid * 4);
    #pragma unroll
    for (int i = 0; i < 2; ++i) {
        const int q = tid + i * 128;            // 0..255
        const int tl = q >> 5, col = (q & 31) * 8;
        cp16(ivb_u + (uint32_t)((tl * SL_D + col) * 2),
             ibase + (size_t)tl * DIM + col);
    }
    cp_commit();
    // Prologue group 1: iv stage 1
    #pragma unroll
    for (int i = 0; i < 2; ++i) {
        const int q = tid + i * 128;
        const int tl = q >> 5, col = (q & 31) * 8;
        cp16(ivb_u + (uint32_t)(((SL_TG + tl) * SL_D + col) * 2),
             ibase + (size_t)(SL_TG + tl) * DIM + col);
    }
    cp_commit();

    for (int s = 0; s < SL_NS; ++s) {
        cp_wait<SL_STAGES - 2>();
        __syncthreads();

        if (s + SL_STAGES - 1 < SL_NS) {
            const int ns = s + SL_STAGES - 1;
            const int st = ns % SL_STAGES;
            #pragma unroll
            for (int i = 0; i < 2; ++i) {
                const int q = tid + i * 128;
                const int tl = q >> 5, col = (q & 31) * 8;
                cp16(ivb_u + (uint32_t)(((st * SL_TG + tl) * SL_D + col) * 2),
                     ibase + (size_t)(ns * SL_TG + tl) * DIM + col);
            }
        }
        cp_commit();

        const int st = s % SL_STAGES;
        #pragma unroll
        for (int j = 0; j < SL_TG; ++j) {
            const int t = s * SL_TG + j;
            const float2 iv = __half22float2(*(const __half2*)(&ivb[st][j][2 * tid]));
            const float4 e0 = *(const float4*)(es + t * KEXP);
            const float4 e1 = *(const float4*)(es + t * KEXP + 4);
            const float ev[KEXP] = {e0.x, e0.y, e0.z, e0.w, e1.x, e1.y, e1.z, e1.w};
            #pragma unroll
            for (int k = 0; k < KEXP; k++) {
                m[k][0] = fmaf(o[k][0], m[k][0], ev[k] * iv.x);
                m[k][1] = fmaf(o[k][1], m[k][1], ev[k] * iv.y);
            }
        }
    }
    #pragma unroll
    for (int k = 0; k < KEXP; k++)
        *(float2*)(g_S + (((size_t)b * NCHUNK + c) * KEXP + k) * DIM + d0) =
            make_float2(m[k][0], m[k][1]);
}

// ---------------------------------------------------------------------------
// Scan phase 2: prefix over 64 chunks.
// grid (BATCH, KEXP, 4), block 128: one (k,d) chain per thread, 128 CTAs.
// Batched register hoists keep MLP high; FMA order unchanged.
// ---------------------------------------------------------------------------
#define PFB 16

__global__ __launch_bounds__(128) void scan_prefix_kernel(const float* __restrict__ o_param) {
    const int b = blockIdx.x;
    const int k = blockIdx.y;
    const int d = blockIdx.z * 128 + threadIdx.x;

    float oL;
    {
        const float op = o_param[k * DIM + d];
        const float ls = fminf(op, 0.0f) - log1pf(expf(-fabsf(op)));
        oL = expf(ls * (INV_TAU * (float)CHUNK));
    }

    float p = 0.0f;
    for (int cb = 0; cb < NCHUNK; cb += PFB) {
        float sv[PFB];
        #pragma unroll
        for (int j = 0; j < PFB; j++)
            sv[j] = g_S[(((size_t)b * NCHUNK + cb + j) * KEXP + k) * DIM + d];
        #pragma unroll
        for (int j = 0; j < PFB; j++) {
            g_P[(((size_t)b * NCHUNK + cb + j) * KEXP + k) * DIM + d] = p;
            p = fmaf(oL, p, sv[j]);
        }
    }
}

// ---------------------------------------------------------------------------
// Scan phase 3 + LayerNorm (CHUNK=64, fp16 iv). 256 threads x 2 d-columns.
// Dynamic SMEM: ybuf[16][512] f32 | es[512] | ss[512] | ivh[2][16][512] fp16
//   = 32768 + 2048 + 2048 + 32768 = 69632 B
// ---------------------------------------------------------------------------
#define TG 16
#define AP_GROUPS (CHUNK/TG)          // 4
#define AP_DYN 69632

__global__ __launch_bounds__(256) void scan_apply_ln_kernel(const float* __restrict__ o_param,
                                                            const float* __restrict__ gamma,
                                                            const float* __restrict__ beta) {
    extern __shared__ float dyn[];
    float (*ybuf)[DIM] = (float(*)[DIM])dyn;
    float* es = dyn + TG * DIM;
    float* ss = es + CHUNK * KEXP;
    __half* ivh = (__half*)(ss + CHUNK * KEXP);   // [2][TG][DIM]
    const uint32_t es_u = smem_to_u32(es);
    const uint32_t ss_u = smem_to_u32(ss);
    const uint32_t ivh_u = smem_to_u32(ivh);
    __shared__ float smu[TG], srstd[TG];

    const int c = blockIdx.x, b = blockIdx.y;
    const int tid = threadIdx.x;
    const int d0 = 2 * tid;
    const int lane = tid & 31, warp = tid >> 5;   // 8 warps

    float o[KEXP][2], m[KEXP][2];
    load_decay2(o_param, d0, INV_TAU, o);
    #pragma unroll
    for (int k = 0; k < KEXP; k++) {
        float2 p = *(const float2*)(g_P + (((size_t)b * NCHUNK + c) * KEXP + k) * DIM + d0);
        m[k][0] = p.x; m[k][1] = p.y;
    }

    const float2 gam = *(const float2*)(gamma + d0);
    const float2 bet = *(const float2*)(beta + d0);

    const size_t rowbase = (size_t)b * SEQ + c * CHUNK;
    const __half* ibase = g_ih + rowbase * DIM;
    const float* ep = g_e + rowbase * KEXP;
    const float* sp = g_s + rowbase * KEXP;

    // Prologue: e chunk + s chunk (2KB each) + iv stage 0 (16x512 halves)
    if (tid < 128)
        cp16(es_u + (uint32_t)(tid * 16), ep + tid * 4);
    else
        cp16(ss_u + (uint32_t)((tid - 128) * 16), sp + (tid - 128) * 4);
    #pragma unroll
    for (int i = 0; i < 4; ++i) {
        const int q = tid + i * 256;               // 0..1023
        const int tl = q >> 6, col = (q & 63) * 8;
        cp16(ivh_u + (uint32_t)((tl * DIM + col) * 2),
             ibase + (size_t)tl * DIM + col);
    }
    cp_commit();

    for (int g = 0; g < AP_GROUPS; ++g) {
        cp_wait<0>();
        __syncthreads();

        if (g + 1 < AP_GROUPS) {
            const int st = (g + 1) & 1;
            #pragma unroll
            for (int i = 0; i < 4; ++i) {
                const int q = tid + i * 256;
                const int tl = q >> 6, col = (q & 63) * 8;
                cp16(ivh_u + (uint32_t)(((st * TG + tl) * DIM + col) * 2),
                     ibase + (size_t)((g + 1) * TG + tl) * DIM + col);
            }
        }
        cp_commit();

        const __half* ivst = ivh + (size_t)(g & 1) * TG * DIM;

        #pragma unroll 4
        for (int tt = 0; tt < TG; ++tt) {
            const int t = g * TG + tt;
            const float2 iv = __half22float2(*(const __half2*)(ivst + tt * DIM + d0));
            const float4 e0 = *(const float4*)(es + t * KEXP);
            const float4 e1 = *(const float4*)(es + t * KEXP + 4);
            const float4 s0 = *(const float4*)(ss + t * KEXP);
            const float4 s1 = *(const float4*)(ss + t * KEXP + 4);
            const float ev[KEXP] = {e0.x, e0.y, e0.z, e0.w, e1.x, e1.y, e1.z, e1.w};
            const float sv[KEXP] = {s0.x, s0.y, s0.z, s0.w, s1.x, s1.y, s1.z, s1.w};
            float ya0 = 0.0f, ya1 = 0.0f;
            #pragma unroll
            for (int k = 0; k < KEXP; k++) {
                m[k][0] = fmaf(o[k][0], m[k][0], ev[k] * iv.x);
                m[k][1] = fmaf(o[k][1], m[k][1], ev[k] * iv.y);
                ya0 = fmaf(sv[k], m[k][0], ya0);
                ya1 = fmaf(sv[k], m[k][1], ya1);
            }
            ybuf[tt][d0] = ya0;
            ybuf[tt][d0 + 1] = ya1;
        }
        __syncthreads();

        // 8 warps: warp w reduces timesteps 2w and 2w+1
        #pragma unroll
        for (int h = 0; h < 2; ++h) {
            const int tt = warp * 2 + h;
            float s1r = 0.0f, s2r = 0.0f;
            #pragma unroll
            for (int j = 0; j < 16; ++j) {
                const float v = ybuf[tt][lane + j * 32];
                s1r += v;
                s2r = fmaf(v, v, s2r);
            }
            #pragma unroll
            for (int off = 16; off > 0; off >>= 1) {
                s1r += __shfl_xor_sync(0xFFFFFFFFu, s1r, off);
                s2r += __shfl_xor_sync(0xFFFFFFFFu, s2r, off);
            }
            if (lane == 0) {
                const float mu = s1r * (1.0f / DIM);
                const float var = s2r * (1.0f / DIM) - mu * mu;
                smu[tt] = mu;
                srstd[tt] = rsqrtf(var + LN_EPS);
            }
        }
        __syncthreads();

        #pragma unroll 4
        for (int tt = 0; tt < TG; ++tt) {
            const size_t row = rowbase + g * TG + tt;
            const float rv0 = fmaf((ybuf[tt][d0] - smu[tt]) * srstd[tt], gam.x, bet.x);
            const float rv1 = fmaf((ybuf[tt][d0 + 1] - smu[tt]) * srstd[tt], gam.y, bet.y);
            *(__half2*)(g_yh + row * DIM + d0) = __floats2half2_rn(rv0, rv1);
        }
    }
}

// ---------------------------------------------------------------------------
// Launch
// ---------------------------------------------------------------------------
extern "C" void kernel_launch(void* const* d_in, const int* in_sizes, int n_in,
                              void* d_out, int out_size) {
    const float* x       = (const float*)d_in[0];
    const float* W_i     = (const float*)d_in[1];
    const float* W_e     = (const float*)d_in[2];
    const float* W_s     = (const float*)d_in[3];
    const float* o_param = (const float*)d_in[4];
    const float* gamma   = (const float*)d_in[5];
    const float* beta    = (const float*)d_in[6];
    const float* W_out   = (const float*)d_in[7];
    float* out = (float*)d_out;

    cudaFuncSetAttribute(scan_apply_ln_kernel,
                         cudaFuncAttributeMaxDynamicSharedMemorySize, AP_DYN);

    convert_all_kernel<<<CVT_XBLOCKS + 512 + 1, 256>>>(x, W_i, W_out, W_e, W_s);
    gemm1_es_kernel<<<dim3(5, 128), 256>>>();
    scan_local_kernel<<<dim3(NCHUNK, BATCH, 2), 128>>>(o_param);
    scan_prefix_kernel<<<dim3(BATCH, KEXP, 4), 128>>>(o_param);
    scan_apply_ln_kernel<<<dim3(NCHUNK, BATCH), 256, AP_DYN>>>(o_param, gamma, beta);
    gemm2_kernel<<<dim3(4, 128), 256>>>(out);
}